// round 14
// baseline (speedup 1.0000x reference)
#include <cuda_runtime.h>
#include <math_constants.h>
#include <cstdint>

#define QLEN  65536
#define EDIM  256
#define NH    8
#define KNBR  16

// Scratch (allocation-free rule: __device__ globals)
__device__ float g_q[(size_t)QLEN * EDIM];
__device__ float g_k[(size_t)QLEN * EDIM];
__device__ float g_v[(size_t)QLEN * EDIM];
__device__ float g_attn[(size_t)QLEN * EDIM];   // tf32-rna-pre-rounded by attn
__device__ uint32_t g_wt[4 * 256 * 256];        // tf32-rounded weights: q,k,v,out

// ---------------------------------------------------------------------------
// PTX helpers
//  R9:  tcgen05 unavailable (harness targets sm_103, not sm_103a).
//  R12: GEMMs are AT the mma.sync tf32 issue ceiling (63us per 64M-row GEMM).
//  R13: attn is AT the LTS gather-request floor (~178us). Serial floor ~435us;
//       only true graph-level concurrency (stream fork) can go below it.
// ---------------------------------------------------------------------------
__device__ __forceinline__ uint32_t f2tf32(float x) {
    uint32_t r;
    asm("cvt.rna.tf32.f32 %0, %1;" : "=r"(r) : "f"(x));
    return r;
}
__device__ __forceinline__ float rnd_tf32(float x) { return __uint_as_float(f2tf32(x)); }

__device__ __forceinline__ void mma_tf32(float c[4], const uint32_t a[4], const uint32_t b[2]) {
    asm volatile(
        "mma.sync.aligned.m16n8k8.row.col.f32.tf32.tf32.f32 "
        "{%0,%1,%2,%3}, {%4,%5,%6,%7}, {%8,%9}, {%0,%1,%2,%3};"
        : "+f"(c[0]), "+f"(c[1]), "+f"(c[2]), "+f"(c[3])
        : "r"(a[0]), "r"(a[1]), "r"(a[2]), "r"(a[3]), "r"(b[0]), "r"(b[1]));
}

__device__ __forceinline__ void cp_async16(void* dst, const void* src) {
    uint32_t d = (uint32_t)__cvta_generic_to_shared(dst);
    asm volatile("cp.async.cg.shared.global [%0], [%1], 16;" :: "r"(d), "l"(src));
}
__device__ __forceinline__ void cp_commit() { asm volatile("cp.async.commit_group;"); }
__device__ __forceinline__ void cp_wait0() { asm volatile("cp.async.wait_group 0;"); }
__device__ __forceinline__ void cp_wait1() { asm volatile("cp.async.wait_group 1;"); }

__device__ __forceinline__ void ldsm_x4(uint32_t r[4], const uint32_t* saddr) {
    uint32_t a = (uint32_t)__cvta_generic_to_shared(saddr);
    asm volatile("ldmatrix.sync.aligned.m8n8.x4.shared.b16 {%0,%1,%2,%3}, [%4];"
        : "=r"(r[0]), "=r"(r[1]), "=r"(r[2]), "=r"(r[3]) : "r"(a));
}

// ---------------------------------------------------------------------------
// Weight pre-convert: fp32 -> tf32 bits
// ---------------------------------------------------------------------------
__global__ void cvt_weights_kernel(const float* __restrict__ Wall,
                                   const float* __restrict__ Wout)
{
    int i = blockIdx.x * 256 + threadIdx.x;
    float v = (i < 3 * 65536) ? Wall[i] : Wout[i - 3 * 65536];
    g_wt[i] = f2tf32(v);
}

// ---------------------------------------------------------------------------
// TF32 GEMM (R8-proven best): 2-stage cp.async, ldmatrix, m16n8k8 HMMA.
// Block 128x128, BK=32, 256 threads = 8 warps (4M x 2N), warp tile 32x64.
// ---------------------------------------------------------------------------
#define SST 36
#define STW 9216
#define GEMM_SMEM (2 * STW * 4)   // 73728 B

__device__ __forceinline__ void gemm_prefetch(const float* __restrict__ A,
                                              const uint32_t* __restrict__ Wt,
                                              uint32_t* stage,
                                              int mBase, int nBase, int kc,
                                              int prow, int kq)
{
    uint32_t* sA = stage;
    uint32_t* sB = stage + 4608;
#pragma unroll
    for (int p = 0; p < 4; p++) {
        int r = prow + p * 32;
        cp_async16(sA + r * SST + kq * 4, A  + (size_t)(mBase + r) * 256 + kc + kq * 4);
        cp_async16(sB + r * SST + kq * 4, Wt + (size_t)(nBase + r) * 256 + kc + kq * 4);
    }
}

template <bool DO_CVT>
__device__ __forceinline__ void gemm256_v2(const float* __restrict__ A,
                                           const uint32_t* __restrict__ Wt,
                                           const float* __restrict__ bias,
                                           float* __restrict__ C,
                                           float scale)
{
    extern __shared__ uint32_t sm[];

    const int tid   = threadIdx.x;
    const int lane  = tid & 31;
    const int warp  = tid >> 5;
    const int g     = lane >> 2;
    const int t     = lane & 3;
    const int warpM = warp >> 1;
    const int warpN = warp & 1;
    const int mBase = blockIdx.y * 128;
    const int nBase = blockIdx.x * 128;
    const int kq    = tid & 7;
    const int prow  = tid >> 3;

    const int lq = lane >> 3;
    const int lr = lane & 7;
    const int aRow  = warpM * 32 + (lq & 1) * 8 + lr;
    const int bRowB = warpN * 64 + (lq & 1) * 8 + lr;
    const int colOf = (lq >> 1) * 4;

    float acc[2][8][4];
#pragma unroll
    for (int ma = 0; ma < 2; ma++)
#pragma unroll
        for (int na = 0; na < 8; na++)
#pragma unroll
            for (int i = 0; i < 4; i++) acc[ma][na][i] = 0.f;

    gemm_prefetch(A, Wt, sm, mBase, nBase, 0, prow, kq);
    cp_commit();

    for (int it = 0; it < 8; ++it) {
        if (it < 7) {
            gemm_prefetch(A, Wt, sm + ((it + 1) & 1) * STW,
                          mBase, nBase, (it + 1) * 32, prow, kq);
            cp_commit();
            cp_wait1();
        } else {
            cp_wait0();
        }
        __syncthreads();

        uint32_t* sA = sm + (it & 1) * STW;
        uint32_t* sB = sA + 4608;

#pragma unroll
        for (int ks = 0; ks < 4; ks++) {
            const int k0 = ks * 8;
            uint32_t a[2][4];
#pragma unroll
            for (int ma = 0; ma < 2; ma++) {
                ldsm_x4(a[ma], sA + (aRow + ma * 16) * SST + k0 + colOf);
                if (DO_CVT) {
#pragma unroll
                    for (int i = 0; i < 4; i++)
                        a[ma][i] = f2tf32(__uint_as_float(a[ma][i]));
                }
            }
            uint32_t b[8][2];
#pragma unroll
            for (int n2 = 0; n2 < 4; n2++) {
                uint32_t r4[4];
                ldsm_x4(r4, sB + (bRowB + n2 * 16) * SST + k0 + colOf);
                b[2 * n2][0] = r4[0]; b[2 * n2 + 1][0] = r4[1];
                b[2 * n2][1] = r4[2]; b[2 * n2 + 1][1] = r4[3];
            }
#pragma unroll
            for (int ma = 0; ma < 2; ma++)
#pragma unroll
                for (int na = 0; na < 8; na++)
                    mma_tf32(acc[ma][na], a[ma], b[na]);
        }
        __syncthreads();
    }

#pragma unroll
    for (int ma = 0; ma < 2; ma++) {
        int row0 = mBase + warpM * 32 + ma * 16 + g;
#pragma unroll
        for (int na = 0; na < 8; na++) {
            int col = nBase + warpN * 64 + na * 8 + t * 2;
            float2 bb = *(const float2*)(bias + col);
            float2 o0, o1;
            o0.x = (acc[ma][na][0] + bb.x) * scale;
            o0.y = (acc[ma][na][1] + bb.y) * scale;
            o1.x = (acc[ma][na][2] + bb.x) * scale;
            o1.y = (acc[ma][na][3] + bb.y) * scale;
            *(float2*)(C + (size_t)row0 * 256 + col) = o0;
            *(float2*)(C + (size_t)(row0 + 8) * 256 + col) = o1;
        }
    }
}

__global__ __launch_bounds__(256, 2)
void qkv_proj_kernel(const float* __restrict__ q_in,
                     const float* __restrict__ k_in,
                     const float* __restrict__ v_in,
                     const float* __restrict__ ball)
{
    const float* A;
    const float* b;
    float* C;
    float scale;
    const uint32_t* Wt;
    if (blockIdx.z == 0) {
        A = q_in; Wt = g_wt;              b = ball;       C = g_q;
        scale = 0.17677669529663687f;     // 1/sqrt(32)
    } else if (blockIdx.z == 1) {
        A = k_in; Wt = g_wt + 65536;      b = ball + 256; C = g_k; scale = 1.f;
    } else {
        A = v_in; Wt = g_wt + 131072;     b = ball + 512; C = g_v; scale = 1.f;
    }
    gemm256_v2<true>(A, Wt, b, C, scale);
}

// outproj over rows [rowOff, rowOff + 16384). g_attn pre-rounded -> no cvt.
__global__ __launch_bounds__(256, 2)
void outproj_chunk_kernel(const float* __restrict__ bout, float* __restrict__ out,
                          int rowOff)
{
    gemm256_v2<false>(g_attn + (size_t)rowOff * EDIM, g_wt + 196608, bout,
                      out + (size_t)rowOff * EDIM, 1.f);
}

// ---------------------------------------------------------------------------
// Attention (R8-proven warp-per-query, full-grid chunks; outputs pre-rounded).
// ---------------------------------------------------------------------------
__global__ __launch_bounds__(256)
void attn_chunk_kernel(const int* __restrict__ idx,
                       float* __restrict__ w_out,
                       int write_w, int unitOff)
{
    const int lane = threadIdx.x & 31;
    const int warp = threadIdx.x >> 5;
    const int q    = (unitOff + blockIdx.x) * 8 + warp;
    const int off  = lane * 8;            // head h = lane>>2, slice s = lane&3

    int myIdx = (lane < KNBR) ? idx[q * KNBR + lane] : -1;

    const float4* qp = (const float4*)(g_q + (size_t)q * EDIM + off);
    float4 q0 = qp[0], q1 = qp[1];

    float logit[KNBR];
#pragma unroll
    for (int j = 0; j < KNBR; j++) {
        int kj  = __shfl_sync(0xffffffffu, myIdx, j);
        int kjc = max(kj, 0);
        const float4* kp = (const float4*)(g_k + (size_t)kjc * EDIM + off);
        float4 k0 = kp[0], k1 = kp[1];
        float p;
        p = q0.x * k0.x;
        p = fmaf(q0.y, k0.y, p);
        p = fmaf(q0.z, k0.z, p);
        p = fmaf(q0.w, k0.w, p);
        p = fmaf(q1.x, k1.x, p);
        p = fmaf(q1.y, k1.y, p);
        p = fmaf(q1.z, k1.z, p);
        p = fmaf(q1.w, k1.w, p);
        p += __shfl_xor_sync(0xffffffffu, p, 1);
        p += __shfl_xor_sync(0xffffffffu, p, 2);
        logit[j] = (kj >= 0) ? p : -CUDART_INF_F;
    }

    float m = logit[0];
#pragma unroll
    for (int j = 1; j < KNBR; j++) m = fmaxf(m, logit[j]);

    float w[KNBR];
    if (m == -CUDART_INF_F) {
#pragma unroll
        for (int j = 0; j < KNBR; j++) w[j] = 0.f;
    } else {
        float s = 0.f;
#pragma unroll
        for (int j = 0; j < KNBR; j++) {
            w[j] = __expf(logit[j] - m);   // exp(-inf)=0 kills invalid slots
            s += w[j];
        }
        float inv = 1.f / s;
#pragma unroll
        for (int j = 0; j < KNBR; j++) w[j] *= inv;
    }

    float o[8];
#pragma unroll
    for (int i = 0; i < 8; i++) o[i] = 0.f;
#pragma unroll
    for (int j = 0; j < KNBR; j++) {
        int kjc = max(__shfl_sync(0xffffffffu, myIdx, j), 0);
        const float4* vp = (const float4*)(g_v + (size_t)kjc * EDIM + off);
        float4 v0 = vp[0], v1 = vp[1];
        float wj = w[j];
        o[0] = fmaf(wj, v0.x, o[0]);
        o[1] = fmaf(wj, v0.y, o[1]);
        o[2] = fmaf(wj, v0.z, o[2]);
        o[3] = fmaf(wj, v0.w, o[3]);
        o[4] = fmaf(wj, v1.x, o[4]);
        o[5] = fmaf(wj, v1.y, o[5]);
        o[6] = fmaf(wj, v1.z, o[6]);
        o[7] = fmaf(wj, v1.w, o[7]);
    }
    float4* op = (float4*)(g_attn + (size_t)q * EDIM + off);
    op[0] = make_float4(rnd_tf32(o[0]), rnd_tf32(o[1]), rnd_tf32(o[2]), rnd_tf32(o[3]));
    op[1] = make_float4(rnd_tf32(o[4]), rnd_tf32(o[5]), rnd_tf32(o[6]), rnd_tf32(o[7]));

    // averaged weights: xor 4,8,16 sums the 8 heads exactly once -> /NH
    if (write_w) {
        float ws = 0.f;
#pragma unroll
        for (int j = 0; j < KNBR; j++) {
            float s = w[j];
            s += __shfl_xor_sync(0xffffffffu, s, 4);
            s += __shfl_xor_sync(0xffffffffu, s, 8);
            s += __shfl_xor_sync(0xffffffffu, s, 16);
            ws = (lane == j) ? s : ws;
        }
        if (lane < KNBR)
            w_out[q * KNBR + lane] = ws * 0.125f;  // / NH
    }
}

// ---------------------------------------------------------------------------
// Launch: multi-stream capture fork. attn chunks on the main (capture) stream;
// each outproj chunk runs on a side stream gated by the matching attn event ->
// parallel graph branches, each kernel at its own natural occupancy.
// ---------------------------------------------------------------------------
#define NCHUNK 4

extern "C" void kernel_launch(void* const* d_in, const int* in_sizes, int n_in,
                              void* d_out, int out_size)
{
    const float* q_in = (const float*)d_in[0];
    const float* k_in = (const float*)d_in[1];
    const float* v_in = (const float*)d_in[2];
    const int*   idx  = (const int*)  d_in[3];
    const float* Wall = (const float*)d_in[4];
    const float* ball = (const float*)d_in[5];
    const float* Wout = (const float*)d_in[6];
    const float* bout = (const float*)d_in[7];
    float* out = (float*)d_out;

    cudaFuncSetAttribute(qkv_proj_kernel,      cudaFuncAttributeMaxDynamicSharedMemorySize, GEMM_SMEM);
    cudaFuncSetAttribute(outproj_chunk_kernel, cudaFuncAttributeMaxDynamicSharedMemorySize, GEMM_SMEM);

    // one-time host-side objects (no device memory)
    static cudaStream_t s1 = nullptr;
    static cudaEvent_t evA[NCHUNK], evJoin;
    static bool forkReady = false;
    static bool initTried = false;
    if (!initTried) {
        initTried = true;
        bool ok = (cudaStreamCreateWithFlags(&s1, cudaStreamNonBlocking) == cudaSuccess);
        for (int i = 0; i < NCHUNK && ok; i++)
            ok = (cudaEventCreateWithFlags(&evA[i], cudaEventDisableTiming) == cudaSuccess);
        if (ok) ok = (cudaEventCreateWithFlags(&evJoin, cudaEventDisableTiming) == cudaSuccess);
        forkReady = ok;
    }

    // 0) weights -> tf32 bits
    cvt_weights_kernel<<<1024, 256>>>(Wall, Wout);

    // 1) fused q/k/v projections
    dim3 gproj(2, 512, 3);
    qkv_proj_kernel<<<gproj, 256, GEMM_SMEM>>>(q_in, k_in, v_in, ball);

    int write_w = (out_size >= QLEN * (EDIM + KNBR)) ? 1 : 0;
    float* w_out = out + (size_t)QLEN * EDIM;

    if (forkReady) {
        // 2) attn chunk i on main stream; outproj chunk i forks onto s1
        for (int i = 0; i < NCHUNK; i++) {
            attn_chunk_kernel<<<8192 / NCHUNK, 256>>>(idx, w_out, write_w,
                                                      i * (8192 / NCHUNK));
            cudaEventRecord(evA[i], 0);
            cudaStreamWaitEvent(s1, evA[i], 0);
            outproj_chunk_kernel<<<dim3(2, QLEN / NCHUNK / 128), 256, GEMM_SMEM, s1>>>(
                bout, out, i * (QLEN / NCHUNK));
        }
        // join side branch back into the capture stream
        cudaEventRecord(evJoin, s1);
        cudaStreamWaitEvent(0, evJoin, 0);
    } else {
        // serial fallback (correct, no overlap)
        for (int i = 0; i < NCHUNK; i++)
            attn_chunk_kernel<<<8192 / NCHUNK, 256>>>(idx, w_out, write_w,
                                                      i * (8192 / NCHUNK));
        for (int i = 0; i < NCHUNK; i++)
            outproj_chunk_kernel<<<dim3(2, QLEN / NCHUNK / 128), 256, GEMM_SMEM>>>(
                bout, out, i * (QLEN / NCHUNK));
    }
}

// round 15
// speedup vs baseline: 1.0756x; 1.0756x over previous
#include <cuda_runtime.h>
#include <math_constants.h>
#include <cstdint>

#define QLEN  65536
#define EDIM  256
#define NH    8
#define KNBR  16

// Scratch (allocation-free rule: __device__ globals)
__device__ float g_q[(size_t)QLEN * EDIM];
__device__ float g_k[(size_t)QLEN * EDIM];
__device__ float g_v[(size_t)QLEN * EDIM];
__device__ float g_attn[(size_t)QLEN * EDIM];   // tf32-rna-pre-rounded by pass2
__device__ float g_w[(size_t)QLEN * 128];       // softmax weights [q][h*16+j]
__device__ uint32_t g_wt[4 * 256 * 256];        // tf32-rounded weights: q,k,v,out

// ---------------------------------------------------------------------------
// PTX helpers
//  R9:  tcgen05 unavailable (harness targets sm_103, not sm_103a).
//  R12: GEMMs AT the mma.sync tf32 issue ceiling (63us per GEMM).
//  R11/R13/R14: four overlap schemes failed (no co-scheduling under capture).
//  R13 ncu: attn DRAM=57.9% -> k+v (128MB) thrash L2 (126MB). This round:
//  two-pass attn, each pass's random working set (64MB) L2-resident.
// ---------------------------------------------------------------------------
__device__ __forceinline__ uint32_t f2tf32(float x) {
    uint32_t r;
    asm("cvt.rna.tf32.f32 %0, %1;" : "=r"(r) : "f"(x));
    return r;
}
__device__ __forceinline__ float rnd_tf32(float x) { return __uint_as_float(f2tf32(x)); }

__device__ __forceinline__ void mma_tf32(float c[4], const uint32_t a[4], const uint32_t b[2]) {
    asm volatile(
        "mma.sync.aligned.m16n8k8.row.col.f32.tf32.tf32.f32 "
        "{%0,%1,%2,%3}, {%4,%5,%6,%7}, {%8,%9}, {%0,%1,%2,%3};"
        : "+f"(c[0]), "+f"(c[1]), "+f"(c[2]), "+f"(c[3])
        : "r"(a[0]), "r"(a[1]), "r"(a[2]), "r"(a[3]), "r"(b[0]), "r"(b[1]));
}

__device__ __forceinline__ void cp_async16(void* dst, const void* src) {
    uint32_t d = (uint32_t)__cvta_generic_to_shared(dst);
    asm volatile("cp.async.cg.shared.global [%0], [%1], 16;" :: "r"(d), "l"(src));
}
__device__ __forceinline__ void cp_commit() { asm volatile("cp.async.commit_group;"); }
__device__ __forceinline__ void cp_wait0() { asm volatile("cp.async.wait_group 0;"); }
__device__ __forceinline__ void cp_wait1() { asm volatile("cp.async.wait_group 1;"); }

__device__ __forceinline__ void ldsm_x4(uint32_t r[4], const uint32_t* saddr) {
    uint32_t a = (uint32_t)__cvta_generic_to_shared(saddr);
    asm volatile("ldmatrix.sync.aligned.m8n8.x4.shared.b16 {%0,%1,%2,%3}, [%4];"
        : "=r"(r[0]), "=r"(r[1]), "=r"(r[2]), "=r"(r[3]) : "r"(a));
}

// ---------------------------------------------------------------------------
// Weight pre-convert: fp32 -> tf32 bits
// ---------------------------------------------------------------------------
__global__ void cvt_weights_kernel(const float* __restrict__ Wall,
                                   const float* __restrict__ Wout)
{
    int i = blockIdx.x * 256 + threadIdx.x;
    float v = (i < 3 * 65536) ? Wall[i] : Wout[i - 3 * 65536];
    g_wt[i] = f2tf32(v);
}

// ---------------------------------------------------------------------------
// TF32 GEMM (R8-proven best): 2-stage cp.async, ldmatrix, m16n8k8 HMMA.
// Block 128x128, BK=32, 256 threads = 8 warps (4M x 2N), warp tile 32x64.
// ---------------------------------------------------------------------------
#define SST 36
#define STW 9216
#define GEMM_SMEM (2 * STW * 4)   // 73728 B

__device__ __forceinline__ void gemm_prefetch(const float* __restrict__ A,
                                              const uint32_t* __restrict__ Wt,
                                              uint32_t* stage,
                                              int mBase, int nBase, int kc,
                                              int prow, int kq)
{
    uint32_t* sA = stage;
    uint32_t* sB = stage + 4608;
#pragma unroll
    for (int p = 0; p < 4; p++) {
        int r = prow + p * 32;
        cp_async16(sA + r * SST + kq * 4, A  + (size_t)(mBase + r) * 256 + kc + kq * 4);
        cp_async16(sB + r * SST + kq * 4, Wt + (size_t)(nBase + r) * 256 + kc + kq * 4);
    }
}

template <bool DO_CVT>
__device__ __forceinline__ void gemm256_v2(const float* __restrict__ A,
                                           const uint32_t* __restrict__ Wt,
                                           const float* __restrict__ bias,
                                           float* __restrict__ C,
                                           float scale)
{
    extern __shared__ uint32_t sm[];

    const int tid   = threadIdx.x;
    const int lane  = tid & 31;
    const int warp  = tid >> 5;
    const int g     = lane >> 2;
    const int t     = lane & 3;
    const int warpM = warp >> 1;
    const int warpN = warp & 1;
    const int mBase = blockIdx.y * 128;
    const int nBase = blockIdx.x * 128;
    const int kq    = tid & 7;
    const int prow  = tid >> 3;

    const int lq = lane >> 3;
    const int lr = lane & 7;
    const int aRow  = warpM * 32 + (lq & 1) * 8 + lr;
    const int bRowB = warpN * 64 + (lq & 1) * 8 + lr;
    const int colOf = (lq >> 1) * 4;

    float acc[2][8][4];
#pragma unroll
    for (int ma = 0; ma < 2; ma++)
#pragma unroll
        for (int na = 0; na < 8; na++)
#pragma unroll
            for (int i = 0; i < 4; i++) acc[ma][na][i] = 0.f;

    gemm_prefetch(A, Wt, sm, mBase, nBase, 0, prow, kq);
    cp_commit();

    for (int it = 0; it < 8; ++it) {
        if (it < 7) {
            gemm_prefetch(A, Wt, sm + ((it + 1) & 1) * STW,
                          mBase, nBase, (it + 1) * 32, prow, kq);
            cp_commit();
            cp_wait1();
        } else {
            cp_wait0();
        }
        __syncthreads();

        uint32_t* sA = sm + (it & 1) * STW;
        uint32_t* sB = sA + 4608;

#pragma unroll
        for (int ks = 0; ks < 4; ks++) {
            const int k0 = ks * 8;
            uint32_t a[2][4];
#pragma unroll
            for (int ma = 0; ma < 2; ma++) {
                ldsm_x4(a[ma], sA + (aRow + ma * 16) * SST + k0 + colOf);
                if (DO_CVT) {
#pragma unroll
                    for (int i = 0; i < 4; i++)
                        a[ma][i] = f2tf32(__uint_as_float(a[ma][i]));
                }
            }
            uint32_t b[8][2];
#pragma unroll
            for (int n2 = 0; n2 < 4; n2++) {
                uint32_t r4[4];
                ldsm_x4(r4, sB + (bRowB + n2 * 16) * SST + k0 + colOf);
                b[2 * n2][0] = r4[0]; b[2 * n2 + 1][0] = r4[1];
                b[2 * n2][1] = r4[2]; b[2 * n2 + 1][1] = r4[3];
            }
#pragma unroll
            for (int ma = 0; ma < 2; ma++)
#pragma unroll
                for (int na = 0; na < 8; na++)
                    mma_tf32(acc[ma][na], a[ma], b[na]);
        }
        __syncthreads();
    }

#pragma unroll
    for (int ma = 0; ma < 2; ma++) {
        int row0 = mBase + warpM * 32 + ma * 16 + g;
#pragma unroll
        for (int na = 0; na < 8; na++) {
            int col = nBase + warpN * 64 + na * 8 + t * 2;
            float2 bb = *(const float2*)(bias + col);
            float2 o0, o1;
            o0.x = (acc[ma][na][0] + bb.x) * scale;
            o0.y = (acc[ma][na][1] + bb.y) * scale;
            o1.x = (acc[ma][na][2] + bb.x) * scale;
            o1.y = (acc[ma][na][3] + bb.y) * scale;
            *(float2*)(C + (size_t)row0 * 256 + col) = o0;
            *(float2*)(C + (size_t)(row0 + 8) * 256 + col) = o1;
        }
    }
}

__global__ __launch_bounds__(256, 2)
void qkv_proj_kernel(const float* __restrict__ q_in,
                     const float* __restrict__ k_in,
                     const float* __restrict__ v_in,
                     const float* __restrict__ ball)
{
    const float* A;
    const float* b;
    float* C;
    float scale;
    const uint32_t* Wt;
    if (blockIdx.z == 0) {
        A = q_in; Wt = g_wt;              b = ball;       C = g_q;
        scale = 0.17677669529663687f;     // 1/sqrt(32)
    } else if (blockIdx.z == 1) {
        A = k_in; Wt = g_wt + 65536;      b = ball + 256; C = g_k; scale = 1.f;
    } else {
        A = v_in; Wt = g_wt + 131072;     b = ball + 512; C = g_v; scale = 1.f;
    }
    gemm256_v2<true>(A, Wt, b, C, scale);
}

__global__ __launch_bounds__(256, 2)
void outproj_kernel(const float* __restrict__ bout, float* __restrict__ out)
{
    // g_attn is tf32-rna-pre-rounded by pass2 -> no cvt needed
    gemm256_v2<false>(g_attn, g_wt + 196608, bout, out, 1.f);
}

// ---------------------------------------------------------------------------
// Attention PASS 1: logits + softmax. Touches only g_q (seq) + g_k (random,
// 64MB -> L2-resident). Writes per-head weights g_w[q][h*16+j] + out1 avg.
// Warp per query; lane covers 8 floats (head h = lane>>2, slice s = lane&3).
// ---------------------------------------------------------------------------
__global__ __launch_bounds__(256)
void attn_pass1_kernel(const int* __restrict__ idx,
                       float* __restrict__ w_out, int write_w)
{
    const int lane = threadIdx.x & 31;
    const int warp = threadIdx.x >> 5;
    const int q    = blockIdx.x * 8 + warp;
    const int off  = lane * 8;
    const int h    = lane >> 2;
    const int s    = lane & 3;

    int myIdx = (lane < KNBR) ? idx[q * KNBR + lane] : -1;

    const float4* qp = (const float4*)(g_q + (size_t)q * EDIM + off);
    float4 q0 = qp[0], q1 = qp[1];

    float logit[KNBR];
#pragma unroll
    for (int j = 0; j < KNBR; j++) {
        int kj  = __shfl_sync(0xffffffffu, myIdx, j);
        int kjc = max(kj, 0);
        const float4* kp = (const float4*)(g_k + (size_t)kjc * EDIM + off);
        float4 k0 = kp[0], k1 = kp[1];
        float p;
        p = q0.x * k0.x;
        p = fmaf(q0.y, k0.y, p);
        p = fmaf(q0.z, k0.z, p);
        p = fmaf(q0.w, k0.w, p);
        p = fmaf(q1.x, k1.x, p);
        p = fmaf(q1.y, k1.y, p);
        p = fmaf(q1.z, k1.z, p);
        p = fmaf(q1.w, k1.w, p);
        p += __shfl_xor_sync(0xffffffffu, p, 1);
        p += __shfl_xor_sync(0xffffffffu, p, 2);
        logit[j] = (kj >= 0) ? p : -CUDART_INF_F;
    }

    float m = logit[0];
#pragma unroll
    for (int j = 1; j < KNBR; j++) m = fmaxf(m, logit[j]);

    float w[KNBR];
    if (m == -CUDART_INF_F) {
#pragma unroll
        for (int j = 0; j < KNBR; j++) w[j] = 0.f;
    } else {
        float sum = 0.f;
#pragma unroll
        for (int j = 0; j < KNBR; j++) {
            w[j] = __expf(logit[j] - m);   // exp(-inf)=0 kills invalid slots
            sum += w[j];
        }
        float inv = 1.f / sum;
#pragma unroll
        for (int j = 0; j < KNBR; j++) w[j] *= inv;
    }

    // store per-head weights: lane (h,s) writes w[j] for j == s (mod 4)
    float* wq = g_w + (size_t)q * 128 + h * 16;
#pragma unroll
    for (int j = 0; j < KNBR; j++)
        if ((j & 3) == s) wq[j] = w[j];

    // averaged weights: xor 4,8,16 sums the 8 heads exactly once -> /NH
    if (write_w) {
        float ws = 0.f;
#pragma unroll
        for (int j = 0; j < KNBR; j++) {
            float t = w[j];
            t += __shfl_xor_sync(0xffffffffu, t, 4);
            t += __shfl_xor_sync(0xffffffffu, t, 8);
            t += __shfl_xor_sync(0xffffffffu, t, 16);
            ws = (lane == j) ? t : ws;
        }
        if (lane < KNBR)
            w_out[q * KNBR + lane] = ws * 0.125f;  // / NH
    }
}

// ---------------------------------------------------------------------------
// Attention PASS 2: weighted V accumulation. Touches only g_w (seq) + g_v
// (random, 64MB -> L2-resident). Writes pre-rounded g_attn.
// ---------------------------------------------------------------------------
__global__ __launch_bounds__(256)
void attn_pass2_kernel(const int* __restrict__ idx)
{
    const int lane = threadIdx.x & 31;
    const int warp = threadIdx.x >> 5;
    const int q    = blockIdx.x * 8 + warp;
    const int off  = lane * 8;
    const int h    = lane >> 2;

    int myIdx = (lane < KNBR) ? idx[q * KNBR + lane] : -1;

    // 16 weights for this lane's head: 4 x float4, broadcast across s-slices
    const float4* wp = (const float4*)(g_w + (size_t)q * 128 + h * 16);
    float4 w0 = wp[0], w1 = wp[1], w2 = wp[2], w3 = wp[3];
    float w[KNBR] = { w0.x, w0.y, w0.z, w0.w, w1.x, w1.y, w1.z, w1.w,
                      w2.x, w2.y, w2.z, w2.w, w3.x, w3.y, w3.z, w3.w };

    float o[8];
#pragma unroll
    for (int i = 0; i < 8; i++) o[i] = 0.f;
#pragma unroll
    for (int j = 0; j < KNBR; j++) {
        int kjc = max(__shfl_sync(0xffffffffu, myIdx, j), 0);
        const float4* vp = (const float4*)(g_v + (size_t)kjc * EDIM + off);
        float4 v0 = vp[0], v1 = vp[1];
        float wj = w[j];
        o[0] = fmaf(wj, v0.x, o[0]);
        o[1] = fmaf(wj, v0.y, o[1]);
        o[2] = fmaf(wj, v0.z, o[2]);
        o[3] = fmaf(wj, v0.w, o[3]);
        o[4] = fmaf(wj, v1.x, o[4]);
        o[5] = fmaf(wj, v1.y, o[5]);
        o[6] = fmaf(wj, v1.z, o[6]);
        o[7] = fmaf(wj, v1.w, o[7]);
    }
    float4* op = (float4*)(g_attn + (size_t)q * EDIM + off);
    op[0] = make_float4(rnd_tf32(o[0]), rnd_tf32(o[1]), rnd_tf32(o[2]), rnd_tf32(o[3]));
    op[1] = make_float4(rnd_tf32(o[4]), rnd_tf32(o[5]), rnd_tf32(o[6]), rnd_tf32(o[7]));
}

// ---------------------------------------------------------------------------
extern "C" void kernel_launch(void* const* d_in, const int* in_sizes, int n_in,
                              void* d_out, int out_size)
{
    const float* q_in = (const float*)d_in[0];
    const float* k_in = (const float*)d_in[1];
    const float* v_in = (const float*)d_in[2];
    const int*   idx  = (const int*)  d_in[3];
    const float* Wall = (const float*)d_in[4];
    const float* ball = (const float*)d_in[5];
    const float* Wout = (const float*)d_in[6];
    const float* bout = (const float*)d_in[7];
    float* out = (float*)d_out;

    cudaFuncSetAttribute(qkv_proj_kernel, cudaFuncAttributeMaxDynamicSharedMemorySize, GEMM_SMEM);
    cudaFuncSetAttribute(outproj_kernel,  cudaFuncAttributeMaxDynamicSharedMemorySize, GEMM_SMEM);

    // 0) weights -> tf32 bits
    cvt_weights_kernel<<<1024, 256>>>(Wall, Wout);

    // 1) fused q/k/v projections
    dim3 gproj(2, 512, 3);
    qkv_proj_kernel<<<gproj, 256, GEMM_SMEM>>>(q_in, k_in, v_in, ball);

    // 2) attention pass 1 (k-only working set) + pass 2 (v-only working set)
    int write_w = (out_size >= QLEN * (EDIM + KNBR)) ? 1 : 0;
    attn_pass1_kernel<<<QLEN / 8, 256>>>(idx, out + (size_t)QLEN * EDIM, write_w);
    attn_pass2_kernel<<<QLEN / 8, 256>>>(idx);

    // 3) output projection -> d_out[0 : Q*E]
    dim3 gout(2, 512, 1);
    outproj_kernel<<<gout, 256, GEMM_SMEM>>>(bout, out);
}

// round 17
// speedup vs baseline: 1.1457x; 1.0651x over previous
#include <cuda_runtime.h>
#include <math_constants.h>
#include <cstdint>

#define QLEN  65536
#define EDIM  256
#define NH    8
#define KNBR  16

// Scratch (allocation-free rule: __device__ globals)
__device__ float g_q[(size_t)QLEN * EDIM];
__device__ float g_k[(size_t)QLEN * EDIM];
__device__ float g_v[(size_t)QLEN * EDIM];
__device__ float g_attn[(size_t)QLEN * EDIM];   // tf32-rna-pre-rounded by pass2
__device__ float g_w[(size_t)QLEN * 128];       // softmax weights [q][h*16+j]
__device__ uint32_t g_wt[4 * 256 * 256];        // tf32-rounded weights: q,k,v,out

// ---------------------------------------------------------------------------
// PTX helpers
//  R9:  tcgen05 unavailable (harness targets sm_103, not sm_103a).
//  R12: GEMMs AT the mma.sync tf32 issue ceiling (63us per GEMM).
//  R11/R13/R14: overlap schemes fail under graph capture — stay serial.
//  R15: two-pass attn (L2-resident gather arrays) WON (429us).
//  R16: .L2::evict_last requires 256-bit loads (.v8.b32) on this target ->
//  use one v8 load per gathered row (also halves LSU request count).
// ---------------------------------------------------------------------------
__device__ __forceinline__ uint32_t f2tf32(float x) {
    uint32_t r;
    asm("cvt.rna.tf32.f32 %0, %1;" : "=r"(r) : "f"(x));
    return r;
}
__device__ __forceinline__ float rnd_tf32(float x) { return __uint_as_float(f2tf32(x)); }

// gather-array load: 8 floats (256-bit), keep in L2 (evict_last), read-only
__device__ __forceinline__ void ldg_keep8(const float* p, float4& a, float4& b) {
    asm volatile("ld.global.nc.L2::evict_last.v8.b32 "
                 "{%0,%1,%2,%3,%4,%5,%6,%7}, [%8];"
        : "=f"(a.x), "=f"(a.y), "=f"(a.z), "=f"(a.w),
          "=f"(b.x), "=f"(b.y), "=f"(b.z), "=f"(b.w) : "l"(p));
}

__device__ __forceinline__ void mma_tf32(float c[4], const uint32_t a[4], const uint32_t b[2]) {
    asm volatile(
        "mma.sync.aligned.m16n8k8.row.col.f32.tf32.tf32.f32 "
        "{%0,%1,%2,%3}, {%4,%5,%6,%7}, {%8,%9}, {%0,%1,%2,%3};"
        : "+f"(c[0]), "+f"(c[1]), "+f"(c[2]), "+f"(c[3])
        : "r"(a[0]), "r"(a[1]), "r"(a[2]), "r"(a[3]), "r"(b[0]), "r"(b[1]));
}

__device__ __forceinline__ void cp_async16(void* dst, const void* src) {
    uint32_t d = (uint32_t)__cvta_generic_to_shared(dst);
    asm volatile("cp.async.cg.shared.global [%0], [%1], 16;" :: "r"(d), "l"(src));
}
__device__ __forceinline__ void cp_commit() { asm volatile("cp.async.commit_group;"); }
__device__ __forceinline__ void cp_wait0() { asm volatile("cp.async.wait_group 0;"); }
__device__ __forceinline__ void cp_wait1() { asm volatile("cp.async.wait_group 1;"); }

__device__ __forceinline__ void ldsm_x4(uint32_t r[4], const uint32_t* saddr) {
    uint32_t a = (uint32_t)__cvta_generic_to_shared(saddr);
    asm volatile("ldmatrix.sync.aligned.m8n8.x4.shared.b16 {%0,%1,%2,%3}, [%4];"
        : "=r"(r[0]), "=r"(r[1]), "=r"(r[2]), "=r"(r[3]) : "r"(a));
}

// ---------------------------------------------------------------------------
// Weight pre-convert: fp32 -> tf32 bits
// ---------------------------------------------------------------------------
__global__ void cvt_weights_kernel(const float* __restrict__ Wall,
                                   const float* __restrict__ Wout)
{
    int i = blockIdx.x * 256 + threadIdx.x;
    float v = (i < 3 * 65536) ? Wall[i] : Wout[i - 3 * 65536];
    g_wt[i] = f2tf32(v);
}

// ---------------------------------------------------------------------------
// TF32 GEMM (R8-proven best): 2-stage cp.async, ldmatrix, m16n8k8 HMMA.
// Block 128x128, BK=32, 256 threads = 8 warps (4M x 2N), warp tile 32x64.
// ---------------------------------------------------------------------------
#define SST 36
#define STW 9216
#define GEMM_SMEM (2 * STW * 4)   // 73728 B

__device__ __forceinline__ void gemm_prefetch(const float* __restrict__ A,
                                              const uint32_t* __restrict__ Wt,
                                              uint32_t* stage,
                                              int mBase, int nBase, int kc,
                                              int prow, int kq)
{
    uint32_t* sA = stage;
    uint32_t* sB = stage + 4608;
#pragma unroll
    for (int p = 0; p < 4; p++) {
        int r = prow + p * 32;
        cp_async16(sA + r * SST + kq * 4, A  + (size_t)(mBase + r) * 256 + kc + kq * 4);
        cp_async16(sB + r * SST + kq * 4, Wt + (size_t)(nBase + r) * 256 + kc + kq * 4);
    }
}

template <bool DO_CVT>
__device__ __forceinline__ void gemm256_v2(const float* __restrict__ A,
                                           const uint32_t* __restrict__ Wt,
                                           const float* __restrict__ bias,
                                           float* __restrict__ C,
                                           float scale)
{
    extern __shared__ uint32_t sm[];

    const int tid   = threadIdx.x;
    const int lane  = tid & 31;
    const int warp  = tid >> 5;
    const int g     = lane >> 2;
    const int t     = lane & 3;
    const int warpM = warp >> 1;
    const int warpN = warp & 1;
    const int mBase = blockIdx.y * 128;
    const int nBase = blockIdx.x * 128;
    const int kq    = tid & 7;
    const int prow  = tid >> 3;

    const int lq = lane >> 3;
    const int lr = lane & 7;
    const int aRow  = warpM * 32 + (lq & 1) * 8 + lr;
    const int bRowB = warpN * 64 + (lq & 1) * 8 + lr;
    const int colOf = (lq >> 1) * 4;

    float acc[2][8][4];
#pragma unroll
    for (int ma = 0; ma < 2; ma++)
#pragma unroll
        for (int na = 0; na < 8; na++)
#pragma unroll
            for (int i = 0; i < 4; i++) acc[ma][na][i] = 0.f;

    gemm_prefetch(A, Wt, sm, mBase, nBase, 0, prow, kq);
    cp_commit();

    for (int it = 0; it < 8; ++it) {
        if (it < 7) {
            gemm_prefetch(A, Wt, sm + ((it + 1) & 1) * STW,
                          mBase, nBase, (it + 1) * 32, prow, kq);
            cp_commit();
            cp_wait1();
        } else {
            cp_wait0();
        }
        __syncthreads();

        uint32_t* sA = sm + (it & 1) * STW;
        uint32_t* sB = sA + 4608;

#pragma unroll
        for (int ks = 0; ks < 4; ks++) {
            const int k0 = ks * 8;
            uint32_t a[2][4];
#pragma unroll
            for (int ma = 0; ma < 2; ma++) {
                ldsm_x4(a[ma], sA + (aRow + ma * 16) * SST + k0 + colOf);
                if (DO_CVT) {
#pragma unroll
                    for (int i = 0; i < 4; i++)
                        a[ma][i] = f2tf32(__uint_as_float(a[ma][i]));
                }
            }
            uint32_t b[8][2];
#pragma unroll
            for (int n2 = 0; n2 < 4; n2++) {
                uint32_t r4[4];
                ldsm_x4(r4, sB + (bRowB + n2 * 16) * SST + k0 + colOf);
                b[2 * n2][0] = r4[0]; b[2 * n2 + 1][0] = r4[1];
                b[2 * n2][1] = r4[2]; b[2 * n2 + 1][1] = r4[3];
            }
#pragma unroll
            for (int ma = 0; ma < 2; ma++)
#pragma unroll
                for (int na = 0; na < 8; na++)
                    mma_tf32(acc[ma][na], a[ma], b[na]);
        }
        __syncthreads();
    }

#pragma unroll
    for (int ma = 0; ma < 2; ma++) {
        int row0 = mBase + warpM * 32 + ma * 16 + g;
#pragma unroll
        for (int na = 0; na < 8; na++) {
            int col = nBase + warpN * 64 + na * 8 + t * 2;
            float2 bb = *(const float2*)(bias + col);
            float2 o0, o1;
            o0.x = (acc[ma][na][0] + bb.x) * scale;
            o0.y = (acc[ma][na][1] + bb.y) * scale;
            o1.x = (acc[ma][na][2] + bb.x) * scale;
            o1.y = (acc[ma][na][3] + bb.y) * scale;
            *(float2*)(C + (size_t)row0 * 256 + col) = o0;
            *(float2*)(C + (size_t)(row0 + 8) * 256 + col) = o1;
        }
    }
}

__global__ __launch_bounds__(256, 2)
void qkv_proj_kernel(const float* __restrict__ q_in,
                     const float* __restrict__ k_in,
                     const float* __restrict__ v_in,
                     const float* __restrict__ ball)
{
    const float* A;
    const float* b;
    float* C;
    float scale;
    const uint32_t* Wt;
    if (blockIdx.z == 0) {
        A = q_in; Wt = g_wt;              b = ball;       C = g_q;
        scale = 0.17677669529663687f;     // 1/sqrt(32)
    } else if (blockIdx.z == 1) {
        A = k_in; Wt = g_wt + 65536;      b = ball + 256; C = g_k; scale = 1.f;
    } else {
        A = v_in; Wt = g_wt + 131072;     b = ball + 512; C = g_v; scale = 1.f;
    }
    gemm256_v2<true>(A, Wt, b, C, scale);
}

__global__ __launch_bounds__(256, 2)
void outproj_kernel(const float* __restrict__ bout, float* __restrict__ out)
{
    // g_attn is tf32-rna-pre-rounded by pass2 -> no cvt needed
    gemm256_v2<false>(g_attn, g_wt + 196608, bout, out, 1.f);
}

// ---------------------------------------------------------------------------
// Attention PASS 1: logits + softmax. Gathered g_k rows: one 256-bit
// evict_last load per lane (keeps 64MB k-array L2-resident, halves requests).
// One-touch q rows use __ldcs. Writes g_w[q][h*16+j] + averaged weights.
// ---------------------------------------------------------------------------
__global__ __launch_bounds__(256)
void attn_pass1_kernel(const int* __restrict__ idx,
                       float* __restrict__ w_out, int write_w)
{
    const int lane = threadIdx.x & 31;
    const int warp = threadIdx.x >> 5;
    const int q    = blockIdx.x * 8 + warp;
    const int off  = lane * 8;
    const int h    = lane >> 2;
    const int s    = lane & 3;

    int myIdx = (lane < KNBR) ? idx[q * KNBR + lane] : -1;

    const float4* qp = (const float4*)(g_q + (size_t)q * EDIM + off);
    float4 q0 = __ldcs(qp), q1 = __ldcs(qp + 1);

    float logit[KNBR];
#pragma unroll
    for (int j = 0; j < KNBR; j++) {
        int kj  = __shfl_sync(0xffffffffu, myIdx, j);
        int kjc = max(kj, 0);
        float4 k0, k1;
        ldg_keep8(g_k + (size_t)kjc * EDIM + off, k0, k1);
        float p;
        p = q0.x * k0.x;
        p = fmaf(q0.y, k0.y, p);
        p = fmaf(q0.z, k0.z, p);
        p = fmaf(q0.w, k0.w, p);
        p = fmaf(q1.x, k1.x, p);
        p = fmaf(q1.y, k1.y, p);
        p = fmaf(q1.z, k1.z, p);
        p = fmaf(q1.w, k1.w, p);
        p += __shfl_xor_sync(0xffffffffu, p, 1);
        p += __shfl_xor_sync(0xffffffffu, p, 2);
        logit[j] = (kj >= 0) ? p : -CUDART_INF_F;
    }

    float m = logit[0];
#pragma unroll
    for (int j = 1; j < KNBR; j++) m = fmaxf(m, logit[j]);

    float w[KNBR];
    if (m == -CUDART_INF_F) {
#pragma unroll
        for (int j = 0; j < KNBR; j++) w[j] = 0.f;
    } else {
        float sum = 0.f;
#pragma unroll
        for (int j = 0; j < KNBR; j++) {
            w[j] = __expf(logit[j] - m);   // exp(-inf)=0 kills invalid slots
            sum += w[j];
        }
        float inv = 1.f / sum;
#pragma unroll
        for (int j = 0; j < KNBR; j++) w[j] *= inv;
    }

    // store per-head weights: lane (h,s) writes w[j] for j == s (mod 4)
    float* wq = g_w + (size_t)q * 128 + h * 16;
#pragma unroll
    for (int j = 0; j < KNBR; j++)
        if ((j & 3) == s) wq[j] = w[j];

    // averaged weights: xor 4,8,16 sums the 8 heads exactly once -> /NH
    if (write_w) {
        float ws = 0.f;
#pragma unroll
        for (int j = 0; j < KNBR; j++) {
            float t = w[j];
            t += __shfl_xor_sync(0xffffffffu, t, 4);
            t += __shfl_xor_sync(0xffffffffu, t, 8);
            t += __shfl_xor_sync(0xffffffffu, t, 16);
            ws = (lane == j) ? t : ws;
        }
        if (lane < KNBR)
            __stcs(&w_out[q * KNBR + lane], ws * 0.125f);  // / NH, streaming
    }
}

// ---------------------------------------------------------------------------
// Attention PASS 2: weighted V accumulation. Gathered g_v rows: one 256-bit
// evict_last load per lane. One-touch g_w reads use __ldcs. Writes pre-rounded
// g_attn (default policy — consumed by outproj next).
// ---------------------------------------------------------------------------
__global__ __launch_bounds__(256)
void attn_pass2_kernel(const int* __restrict__ idx)
{
    const int lane = threadIdx.x & 31;
    const int warp = threadIdx.x >> 5;
    const int q    = blockIdx.x * 8 + warp;
    const int off  = lane * 8;
    const int h    = lane >> 2;

    int myIdx = (lane < KNBR) ? idx[q * KNBR + lane] : -1;

    // 16 weights for this lane's head: 4 x float4, broadcast across s-slices
    const float4* wp = (const float4*)(g_w + (size_t)q * 128 + h * 16);
    float4 w0 = __ldcs(wp), w1 = __ldcs(wp + 1);
    float4 w2 = __ldcs(wp + 2), w3 = __ldcs(wp + 3);
    float w[KNBR] = { w0.x, w0.y, w0.z, w0.w, w1.x, w1.y, w1.z, w1.w,
                      w2.x, w2.y, w2.z, w2.w, w3.x, w3.y, w3.z, w3.w };

    float o[8];
#pragma unroll
    for (int i = 0; i < 8; i++) o[i] = 0.f;
#pragma unroll
    for (int j = 0; j < KNBR; j++) {
        int kjc = max(__shfl_sync(0xffffffffu, myIdx, j), 0);
        float4 v0, v1;
        ldg_keep8(g_v + (size_t)kjc * EDIM + off, v0, v1);
        float wj = w[j];
        o[0] = fmaf(wj, v0.x, o[0]);
        o[1] = fmaf(wj, v0.y, o[1]);
        o[2] = fmaf(wj, v0.z, o[2]);
        o[3] = fmaf(wj, v0.w, o[3]);
        o[4] = fmaf(wj, v1.x, o[4]);
        o[5] = fmaf(wj, v1.y, o[5]);
        o[6] = fmaf(wj, v1.z, o[6]);
        o[7] = fmaf(wj, v1.w, o[7]);
    }
    float4* op = (float4*)(g_attn + (size_t)q * EDIM + off);
    op[0] = make_float4(rnd_tf32(o[0]), rnd_tf32(o[1]), rnd_tf32(o[2]), rnd_tf32(o[3]));
    op[1] = make_float4(rnd_tf32(o[4]), rnd_tf32(o[5]), rnd_tf32(o[6]), rnd_tf32(o[7]));
}

// ---------------------------------------------------------------------------
extern "C" void kernel_launch(void* const* d_in, const int* in_sizes, int n_in,
                              void* d_out, int out_size)
{
    const float* q_in = (const float*)d_in[0];
    const float* k_in = (const float*)d_in[1];
    const float* v_in = (const float*)d_in[2];
    const int*   idx  = (const int*)  d_in[3];
    const float* Wall = (const float*)d_in[4];
    const float* ball = (const float*)d_in[5];
    const float* Wout = (const float*)d_in[6];
    const float* bout = (const float*)d_in[7];
    float* out = (float*)d_out;

    cudaFuncSetAttribute(qkv_proj_kernel, cudaFuncAttributeMaxDynamicSharedMemorySize, GEMM_SMEM);
    cudaFuncSetAttribute(outproj_kernel,  cudaFuncAttributeMaxDynamicSharedMemorySize, GEMM_SMEM);

    // 0) weights -> tf32 bits
    cvt_weights_kernel<<<1024, 256>>>(Wall, Wout);

    // 1) fused q/k/v projections
    dim3 gproj(2, 512, 3);
    qkv_proj_kernel<<<gproj, 256, GEMM_SMEM>>>(q_in, k_in, v_in, ball);

    // 2) attention pass 1 (k-only working set) + pass 2 (v-only working set)
    int write_w = (out_size >= QLEN * (EDIM + KNBR)) ? 1 : 0;
    attn_pass1_kernel<<<QLEN / 8, 256>>>(idx, out + (size_t)QLEN * EDIM, write_w);
    attn_pass2_kernel<<<QLEN / 8, 256>>>(idx);

    // 3) output projection -> d_out[0 : Q*E]
    dim3 gout(2, 512, 1);
    outproj_kernel<<<gout, 256, GEMM_SMEM>>>(bout, out);
}